// round 9
// baseline (speedup 1.0000x reference)
#include <cuda_runtime.h>

typedef unsigned long long u64;

// ---------------------------------------------------------------------------
// Compile-time CNOT permutation tables.
// Qubit q lives in bit (3-q). CNOT(c,t): flip bit(3-t) if bit(3-c) set (linear).
// ---------------------------------------------------------------------------
struct Tables {
    int pcol[7][4];   // P_l applied to basis indices {1,2,4,8}
    int xm[6][4];     // P_l^{-1}(8>>q): shuffle-xor mask for gate (l,q)
};

__host__ __device__ constexpr int cnot_k(int k, int c, int t) {
    return ((k >> (3 - c)) & 1) ? (k ^ (8 >> t)) : k;
}
__host__ __device__ constexpr int layer_perm(int k, int l) {
    const int r = l % 3 + 1;
    for (int q = 0; q < 4; q++) k = cnot_k(k, q, (q + r) & 3);
    return k;
}
__host__ __device__ constexpr Tables make_tables() {
    Tables T{};
    int P[7][16]{};
    for (int a = 0; a < 16; a++) P[0][a] = a;
    for (int l = 0; l < 6; l++)
        for (int a = 0; a < 16; a++) P[l + 1][a] = layer_perm(P[l][a], l);
    for (int l = 0; l < 7; l++)
        for (int b = 0; b < 4; b++) T.pcol[l][b] = P[l][1 << b];
    for (int l = 0; l < 6; l++)
        for (int q = 0; q < 4; q++) {
            const int m = 8 >> q;
            for (int a = 0; a < 16; a++)
                if (P[l][a] == m) T.xm[l][q] = a;
        }
    return T;
}

// ---------------------------------------------------------------------------
// Packed f32x2 helpers
// ---------------------------------------------------------------------------
__device__ __forceinline__ u64 pk2(float lo, float hi) {
    u64 r; asm("mov.b64 %0, {%1, %2};" : "=l"(r) : "f"(lo), "f"(hi)); return r;
}
__device__ __forceinline__ void upk(float& lo, float& hi, u64 v) {
    asm("mov.b64 {%0, %1}, %2;" : "=f"(lo), "=f"(hi) : "l"(v));
}
__device__ __forceinline__ u64 pfma(u64 a, u64 b, u64 c) {
    u64 d; asm("fma.rn.f32x2 %0, %1, %2, %3;" : "=l"(d) : "l"(a), "l"(b), "l"(c)); return d;
}

// ---------------------------------------------------------------------------
// Fused kernel: each block builds W[4][81] in shared (redundantly), then
// computes 256 samples via a Horner contraction over the 4 qubits.
// ---------------------------------------------------------------------------
__global__ void __launch_bounds__(256) qc_fused(const float*  __restrict__ rot,
                                                const float4* __restrict__ x,
                                                float4*       __restrict__ out,
                                                int B) {
    constexpr Tables TBL = make_tables();

    __shared__ float2 ssc[72];                 // (sin, cos) per derived angle
    __shared__ float2 sU[256];                 // Utilde[m*16 + col]
    __shared__ float  sA[1024];                // A[q][j*16+k]
    __shared__ __align__(16) float4 sW4[81];   // W[q][m] as float4 over q

    const int t = threadIdx.x;
    const int i = blockIdx.x * 256 + t;

    // ---- Hoisted sample load + sincos: hides GMEM/MUFU latency under W build
    const bool valid = (i < B);
    const float4 xx = valid ? x[i] : make_float4(0.f, 0.f, 0.f, 0.f);
    float c0, s0, c1, s1, c2, s2, c3, s3;
    __sincosf(xx.x, &s0, &c0);
    __sincosf(xx.y, &s1, &c1);
    __sincosf(xx.z, &s2, &c2);
    __sincosf(xx.w, &s3, &c3);

    // --- Stage A: sincos table of the rotation angles ---------------------
    if (t < 72) {
        const int g = t / 3, c = t % 3;
        const float phi   = rot[g * 3 + 0];
        const float theta = rot[g * 3 + 1];
        const float omega = rot[g * 3 + 2];
        float ang;
        if      (c == 0) ang =  0.5f * theta;
        else if (c == 1) ang = -0.5f * (phi + omega);
        else             ang =  0.5f * (phi - omega);
        float s, cc;
        __sincosf(ang, &s, &cc);
        ssc[t] = make_float2(s, cc);
    }
    __syncthreads();

    // --- Stage B: 256-way column propagation (16 cols x 16 amps) ----------
    {
        const int col = t >> 4;       // which basis column this thread propagates
        const int a   = t & 15;       // initial amplitude label

        float vr = (a == col) ? 1.f : 0.f;
        float vi = 0.f;

#pragma unroll
        for (int l = 0; l < 6; l++) {
            const int kl = ((a & 1) ? TBL.pcol[l][0] : 0)
                         ^ ((a & 2) ? TBL.pcol[l][1] : 0)
                         ^ ((a & 4) ? TBL.pcol[l][2] : 0)
                         ^ ((a & 8) ? TBL.pcol[l][3] : 0);
#pragma unroll
            for (int q = 0; q < 4; q++) {
                const int g = l * 4 + q;
                const float st  = ssc[g * 3 + 0].x, ct  = ssc[g * 3 + 0].y;
                const float epi = ssc[g * 3 + 1].x, epr = ssc[g * 3 + 1].y;
                const float emi = ssc[g * 3 + 2].x, emr = ssc[g * 3 + 2].y;

                const float u00r =  epr * ct, u00i =  epi * ct;
                const float u01r = -emr * st, u01i = -emi * st;
                const float u10r =  emr * st, u10i = -emi * st;
                const float u11r =  epr * ct, u11i = -epi * ct;

                const bool hi = (kl >> (3 - q)) & 1;
                const int xmask = TBL.xm[l][q];   // partner lane = lane ^ xmask (<16)

                const float pr = __shfl_xor_sync(0xFFFFFFFF, vr, xmask);
                const float pi = __shfl_xor_sync(0xFFFFFFFF, vi, xmask);

                const float lor = hi ? pr : vr, loi = hi ? pi : vi;
                const float hir = hi ? vr : pr, hii = hi ? vi : pi;
                const float cAr = hi ? u10r : u00r, cAi = hi ? u10i : u00i;
                const float cBr = hi ? u11r : u01r, cBi = hi ? u11i : u01i;

                vr = cAr * lor - cAi * loi + cBr * hir - cBi * hii;
                vi = cAr * loi + cAi * lor + cBr * hii + cBi * hir;
            }
        }

        const int m = ((a & 1) ? TBL.pcol[6][0] : 0)
                    ^ ((a & 2) ? TBL.pcol[6][1] : 0)
                    ^ ((a & 4) ? TBL.pcol[6][2] : 0)
                    ^ ((a & 8) ? TBL.pcol[6][3] : 0);

        // fold (-i)^popcount(col) into this column
        const int pc = __popc(col) & 3;
        float nr, ni;
        if      (pc == 0) { nr =  vr; ni =  vi; }
        else if (pc == 1) { nr =  vi; ni = -vr; }
        else if (pc == 2) { nr = -vr; ni = -vi; }
        else              { nr = -vi; ni =  vr; }
        sU[m * 16 + col] = make_float2(nr, ni);
    }
    __syncthreads();

    // --- Stage C: A_q[j,k] -------------------------------------------------
#pragma unroll
    for (int idx = t; idx < 1024; idx += 256) {
        const int qo = idx >> 8;
        const int jk = idx & 255;
        const int j = jk >> 4, k = jk & 15;
        const int bitpos = 3 - qo;
        float acc = 0.f;
#pragma unroll
        for (int m = 0; m < 16; m++) {
            const float2 uj = sU[m * 16 + j];
            const float2 uk = sU[m * 16 + k];
            const float v = uj.x * uk.x + uj.y * uk.y;
            acc += ((m >> bitpos) & 1) ? -v : v;
        }
        sA[idx] = acc;
    }
    __syncthreads();

    // --- Stage D: basis change -> sW4 --------------------------------------
    for (int idx = t; idx < 324; idx += 256) {
        const int m  = idx >> 2;
        const int qo = idx & 3;
        int md[4];
        md[0] = m / 27; md[1] = (m / 9) % 3; md[2] = (m / 3) % 3; md[3] = m % 3;

        float acc = 0.f;
#pragma unroll
        for (int sel = 0; sel < 16; sel++) {
            int j = 0, k = 0;
            float sgn = 1.f;
#pragma unroll
            for (int q = 0; q < 4; q++) {
                const int b = (sel >> (3 - q)) & 1;
                int jkq;
                if (md[q] == 0) {
                    jkq = b ? 3 : 0;
                } else if (md[q] == 1) {
                    jkq = b ? 3 : 0;
                    if (b) sgn = -sgn;
                } else {
                    jkq = b ? 2 : 1;
                }
                j |= (jkq >> 1) << (3 - q);
                k |= (jkq & 1)  << (3 - q);
            }
            acc += sgn * sA[qo * 256 + j * 16 + k];
        }
        ((float*)sW4)[m * 4 + qo] = acc * 0.0625f;
    }
    __syncthreads();

    // --- Per-sample Horner contraction -------------------------------------
    if (!valid) return;

    const u64 C0p = pk2(c0, c0), S0p = pk2(s0, s0);
    const u64 C1p = pk2(c1, c1), S1p = pk2(s1, s1);
    const u64 C2p = pk2(c2, c2), S2p = pk2(s2, s2);
    const u64 C3p = pk2(c3, c3), S3p = pk2(s3, s3);

    u64 fA[3], fB[3];
#pragma unroll
    for (int m0 = 0; m0 < 3; m0++) {
        u64 gA[3], gB[3];
#pragma unroll
        for (int m1 = 0; m1 < 3; m1++) {
            u64 tA[3], tB[3];
#pragma unroll
            for (int m2 = 0; m2 < 3; m2++) {
                const int base = ((m0 * 3 + m1) * 3 + m2) * 3;
                const ulonglong2 w0 = ((const ulonglong2*)sW4)[base + 0];
                const ulonglong2 w1 = ((const ulonglong2*)sW4)[base + 1];
                const ulonglong2 w2 = ((const ulonglong2*)sW4)[base + 2];
                tA[m2] = pfma(S3p, w2.x, pfma(C3p, w1.x, w0.x));
                tB[m2] = pfma(S3p, w2.y, pfma(C3p, w1.y, w0.y));
            }
            gA[m1] = pfma(S2p, tA[2], pfma(C2p, tA[1], tA[0]));
            gB[m1] = pfma(S2p, tB[2], pfma(C2p, tB[1], tB[0]));
        }
        fA[m0] = pfma(S1p, gA[2], pfma(C1p, gA[1], gA[0]));
        fB[m0] = pfma(S1p, gB[2], pfma(C1p, gB[1], gB[0]));
    }
    const u64 outA = pfma(S0p, fA[2], pfma(C0p, fA[1], fA[0]));
    const u64 outB = pfma(S0p, fB[2], pfma(C0p, fB[1], fB[0]));

    float o0, o1, o2, o3;
    upk(o0, o1, outA);
    upk(o2, o3, outB);
    out[i] = make_float4(o0, o1, o2, o3);
}

// ---------------------------------------------------------------------------
extern "C" void kernel_launch(void* const* d_in, const int* in_sizes, int n_in,
                              void* d_out, int out_size) {
    const float* d_x   = (const float*)d_in[0];
    const float* d_rot = (const float*)d_in[1];
    int nx = in_sizes[0];
    if (n_in >= 2 && in_sizes[0] == 72) {
        d_x   = (const float*)d_in[1];
        d_rot = (const float*)d_in[0];
        nx    = in_sizes[1];
    }
    const int B = nx / 4;

    const int threads = 256;
    const int blocks  = (B + threads - 1) / threads;
    qc_fused<<<blocks, threads>>>(d_rot, (const float4*)d_x, (float4*)d_out, B);
}

// round 10
// speedup vs baseline: 1.4030x; 1.4030x over previous
#include <cuda_runtime.h>

typedef unsigned long long u64;

// W coefficients: g_W4[m] = float4(W[0][m], W[1][m], W[2][m], W[3][m]),
// m = m0*27 + m1*9 + m2*3 + m3, basis per qubit: (1, cos x_q, sin x_q).
__device__ float4 g_W4[81];

// ---------------------------------------------------------------------------
// Compile-time CNOT permutation tables.
// ---------------------------------------------------------------------------
struct Tables {
    int pcol[7][4];   // P_l applied to basis indices {1,2,4,8}
    int xm[6][4];     // P_l^{-1}(8>>q): shuffle-xor mask for gate (l,q)
};

__host__ __device__ constexpr int cnot_k(int k, int c, int t) {
    return ((k >> (3 - c)) & 1) ? (k ^ (8 >> t)) : k;
}
__host__ __device__ constexpr int layer_perm(int k, int l) {
    const int r = l % 3 + 1;
    for (int q = 0; q < 4; q++) k = cnot_k(k, q, (q + r) & 3);
    return k;
}
__host__ __device__ constexpr Tables make_tables() {
    Tables T{};
    int P[7][16]{};
    for (int a = 0; a < 16; a++) P[0][a] = a;
    for (int l = 0; l < 6; l++)
        for (int a = 0; a < 16; a++) P[l + 1][a] = layer_perm(P[l][a], l);
    for (int l = 0; l < 7; l++)
        for (int b = 0; b < 4; b++) T.pcol[l][b] = P[l][1 << b];
    for (int l = 0; l < 6; l++)
        for (int q = 0; q < 4; q++) {
            const int m = 8 >> q;
            for (int a = 0; a < 16; a++)
                if (P[l][a] == m) T.xm[l][q] = a;
        }
    return T;
}

// ---------------------------------------------------------------------------
// Kernel 1: build W[4][81]. One block, 256 threads. (identical to R8)
// ---------------------------------------------------------------------------
__global__ void __launch_bounds__(256) build_W(const float* __restrict__ rot) {
    constexpr Tables TBL = make_tables();

    __shared__ float2 ssc[72];     // (sin, cos) per derived angle
    __shared__ float2 sU[256];     // Utilde[m*16 + col]
    __shared__ float  sA[1024];    // A[q][j*16+k]

    const int t = threadIdx.x;

    // --- Stage A: sincos table -------------------------------------------
    if (t < 72) {
        const int g = t / 3, c = t % 3;
        const float phi   = rot[g * 3 + 0];
        const float theta = rot[g * 3 + 1];
        const float omega = rot[g * 3 + 2];
        float ang;
        if      (c == 0) ang =  0.5f * theta;
        else if (c == 1) ang = -0.5f * (phi + omega);
        else             ang =  0.5f * (phi - omega);
        float s, cc;
        __sincosf(ang, &s, &cc);
        ssc[t] = make_float2(s, cc);
    }
    __syncthreads();

    // --- Stage B: 256-way column propagation ------------------------------
    {
        const int col = t >> 4;
        const int a   = t & 15;

        float vr = (a == col) ? 1.f : 0.f;
        float vi = 0.f;

#pragma unroll
        for (int l = 0; l < 6; l++) {
            const int kl = ((a & 1) ? TBL.pcol[l][0] : 0)
                         ^ ((a & 2) ? TBL.pcol[l][1] : 0)
                         ^ ((a & 4) ? TBL.pcol[l][2] : 0)
                         ^ ((a & 8) ? TBL.pcol[l][3] : 0);
#pragma unroll
            for (int q = 0; q < 4; q++) {
                const int g = l * 4 + q;
                const float st  = ssc[g * 3 + 0].x, ct  = ssc[g * 3 + 0].y;
                const float epi = ssc[g * 3 + 1].x, epr = ssc[g * 3 + 1].y;
                const float emi = ssc[g * 3 + 2].x, emr = ssc[g * 3 + 2].y;

                const float u00r =  epr * ct, u00i =  epi * ct;
                const float u01r = -emr * st, u01i = -emi * st;
                const float u10r =  emr * st, u10i = -emi * st;
                const float u11r =  epr * ct, u11i = -epi * ct;

                const bool hi = (kl >> (3 - q)) & 1;
                const int xmask = TBL.xm[l][q];

                const float pr = __shfl_xor_sync(0xFFFFFFFF, vr, xmask);
                const float pi = __shfl_xor_sync(0xFFFFFFFF, vi, xmask);

                const float lor = hi ? pr : vr, loi = hi ? pi : vi;
                const float hir = hi ? vr : pr, hii = hi ? vi : pi;
                const float cAr = hi ? u10r : u00r, cAi = hi ? u10i : u00i;
                const float cBr = hi ? u11r : u01r, cBi = hi ? u11i : u01i;

                vr = cAr * lor - cAi * loi + cBr * hir - cBi * hii;
                vi = cAr * loi + cAi * lor + cBr * hii + cBi * hir;
            }
        }

        const int m = ((a & 1) ? TBL.pcol[6][0] : 0)
                    ^ ((a & 2) ? TBL.pcol[6][1] : 0)
                    ^ ((a & 4) ? TBL.pcol[6][2] : 0)
                    ^ ((a & 8) ? TBL.pcol[6][3] : 0);

        const int pc = __popc(col) & 3;
        float nr, ni;
        if      (pc == 0) { nr =  vr; ni =  vi; }
        else if (pc == 1) { nr =  vi; ni = -vr; }
        else if (pc == 2) { nr = -vr; ni = -vi; }
        else              { nr = -vi; ni =  vr; }
        sU[m * 16 + col] = make_float2(nr, ni);
    }
    __syncthreads();

    // --- Stage C: A_q[j,k] -----------------------------------------------
#pragma unroll
    for (int idx = t; idx < 1024; idx += 256) {
        const int qo = idx >> 8;
        const int jk = idx & 255;
        const int j = jk >> 4, k = jk & 15;
        const int bitpos = 3 - qo;
        float acc = 0.f;
#pragma unroll
        for (int m = 0; m < 16; m++) {
            const float2 uj = sU[m * 16 + j];
            const float2 uk = sU[m * 16 + k];
            const float v = uj.x * uk.x + uj.y * uk.y;
            acc += ((m >> bitpos) & 1) ? -v : v;
        }
        sA[idx] = acc;
    }
    __syncthreads();

    // --- Stage D: basis change -> W --------------------------------------
    for (int idx = t; idx < 324; idx += 256) {
        const int m  = idx >> 2;
        const int qo = idx & 3;
        int md[4];
        md[0] = m / 27; md[1] = (m / 9) % 3; md[2] = (m / 3) % 3; md[3] = m % 3;

        float acc = 0.f;
#pragma unroll
        for (int sel = 0; sel < 16; sel++) {
            int j = 0, k = 0;
            float sgn = 1.f;
#pragma unroll
            for (int q = 0; q < 4; q++) {
                const int b = (sel >> (3 - q)) & 1;
                int jkq;
                if (md[q] == 0) {
                    jkq = b ? 3 : 0;
                } else if (md[q] == 1) {
                    jkq = b ? 3 : 0;
                    if (b) sgn = -sgn;
                } else {
                    jkq = b ? 2 : 1;
                }
                j |= (jkq >> 1) << (3 - q);
                k |= (jkq & 1)  << (3 - q);
            }
            acc += sgn * sA[qo * 256 + j * 16 + k];
        }
        ((float*)g_W4)[m * 4 + qo] = acc * 0.0625f;
    }
}

// ---------------------------------------------------------------------------
// Packed f32x2 helpers
// ---------------------------------------------------------------------------
__device__ __forceinline__ u64 pk2(float lo, float hi) {
    u64 r; asm("mov.b64 %0, {%1, %2};" : "=l"(r) : "f"(lo), "f"(hi)); return r;
}
__device__ __forceinline__ void upk(float& lo, float& hi, u64 v) {
    asm("mov.b64 {%0, %1}, %2;" : "=f"(lo), "=f"(hi) : "l"(v));
}
__device__ __forceinline__ u64 pfma(u64 a, u64 b, u64 c) {
    u64 d; asm("fma.rn.f32x2 %0, %1, %2, %3;" : "=l"(d) : "l"(a), "l"(b), "l"(c)); return d;
}

// ---------------------------------------------------------------------------
// Kernel 2: one thread = one sample; Horner contraction over 4 qubits.
// f32x2 lanes pack the q-axis: accA = (out_q0, out_q1), accB = (q2, q3).
// 128-thread blocks for better SM wave balance (1024 blocks ~ 6.9/SM).
// ---------------------------------------------------------------------------
__global__ void __launch_bounds__(128) qc_forward(const float4* __restrict__ x,
                                                  float4* __restrict__ out,
                                                  int B) {
    __shared__ __align__(16) float4 sW4[81];
    const int tid = threadIdx.x;
    if (tid < 81) sW4[tid] = g_W4[tid];
    __syncthreads();

    const int i = blockIdx.x * 128 + tid;
    if (i >= B) return;

    const float4 xx = x[i];
    float c0, s0, c1, s1, c2, s2, c3, s3;
    __sincosf(xx.x, &s0, &c0);
    __sincosf(xx.y, &s1, &c1);
    __sincosf(xx.z, &s2, &c2);
    __sincosf(xx.w, &s3, &c3);

    const u64 C0p = pk2(c0, c0), S0p = pk2(s0, s0);
    const u64 C1p = pk2(c1, c1), S1p = pk2(s1, s1);
    const u64 C2p = pk2(c2, c2), S2p = pk2(s2, s2);
    const u64 C3p = pk2(c3, c3), S3p = pk2(s3, s3);

    u64 fA[3], fB[3];
#pragma unroll
    for (int m0 = 0; m0 < 3; m0++) {
        u64 gA[3], gB[3];
#pragma unroll
        for (int m1 = 0; m1 < 3; m1++) {
            u64 tA[3], tB[3];
#pragma unroll
            for (int m2 = 0; m2 < 3; m2++) {
                const int base = ((m0 * 3 + m1) * 3 + m2) * 3;
                const ulonglong2 w0 = ((const ulonglong2*)sW4)[base + 0];
                const ulonglong2 w1 = ((const ulonglong2*)sW4)[base + 1];
                const ulonglong2 w2 = ((const ulonglong2*)sW4)[base + 2];
                tA[m2] = pfma(S3p, w2.x, pfma(C3p, w1.x, w0.x));
                tB[m2] = pfma(S3p, w2.y, pfma(C3p, w1.y, w0.y));
            }
            gA[m1] = pfma(S2p, tA[2], pfma(C2p, tA[1], tA[0]));
            gB[m1] = pfma(S2p, tB[2], pfma(C2p, tB[1], tB[0]));
        }
        fA[m0] = pfma(S1p, gA[2], pfma(C1p, gA[1], gA[0]));
        fB[m0] = pfma(S1p, gB[2], pfma(C1p, gB[1], gB[0]));
    }
    const u64 outA = pfma(S0p, fA[2], pfma(C0p, fA[1], fA[0]));
    const u64 outB = pfma(S0p, fB[2], pfma(C0p, fB[1], fB[0]));

    float o0, o1, o2, o3;
    upk(o0, o1, outA);
    upk(o2, o3, outB);
    out[i] = make_float4(o0, o1, o2, o3);
}

// ---------------------------------------------------------------------------
extern "C" void kernel_launch(void* const* d_in, const int* in_sizes, int n_in,
                              void* d_out, int out_size) {
    const float* d_x   = (const float*)d_in[0];
    const float* d_rot = (const float*)d_in[1];
    int nx = in_sizes[0];
    if (n_in >= 2 && in_sizes[0] == 72) {
        d_x   = (const float*)d_in[1];
        d_rot = (const float*)d_in[0];
        nx    = in_sizes[1];
    }
    const int B = nx / 4;

    build_W<<<1, 256>>>(d_rot);
    const int threads = 128;
    const int blocks  = (B + threads - 1) / threads;
    qc_forward<<<blocks, threads>>>((const float4*)d_x, (float4*)d_out, B);
}